// round 11
// baseline (speedup 1.0000x reference)
#include <cuda_runtime.h>
#include <cuda_bf16.h>
#include <cuda_fp16.h>
#include <math.h>
#include <stdint.h>

#define N_NODES 50000
#define N_EDGES 800000
#define IN_DIM  512
#define HIDDEN  128
#define OUT_DIM 64
#define EPS_F   0.3f
#define SCAN_NB 49           // ceil(50000/1024)

// ---------------- scratch (device globals; no allocation allowed) -----------
__device__ __half g_h0h[N_NODES * HIDDEN];   // raw fp16 (gathers + residual + gate_proj)
__device__ __half g_hAh[N_NODES * HIDDEN];   // layer-0 out fp16
__device__ float  g_hB [N_NODES * HIDDEN];   // layer-1 out fp32 (head input)
__device__ float  g_sdst[N_NODES];
__device__ float  g_ssrc[N_NODES];
__device__ int    g_counts[N_NODES];
__device__ int    g_rowptr[N_NODES + 1];
__device__ int    g_cursor[N_NODES];
__device__ int    g_psrc[N_EDGES];           // src per CSR position
__device__ int    g_pdst[N_EDGES];           // dst per CSR position
__device__ int2   g_pedge[N_EDGES];          // {src, coef bits} per CSR position
__device__ int    g_blocksums[64];
__device__ __nv_bfloat16 g_w_hi[HIDDEN * IN_DIM];
__device__ __nv_bfloat16 g_w_lo[HIDDEN * IN_DIM];

// ---------------- W split-precision conversion (branch A) -------------------
__global__ void wconv_kernel(const float* __restrict__ W) {
    int i = blockIdx.x * blockDim.x + threadIdx.x;
    if (i < HIDDEN * IN_DIM) {
        float v = W[i];
        __nv_bfloat16 h = __float2bfloat16_rn(v);
        g_w_hi[i] = h;
        g_w_lo[i] = __float2bfloat16_rn(v - __bfloat162float(h));
    }
}

// ---------------- GEMM1 via split-bf16 tensor cores --------------------------
#define GP 20  // smem row pitch in 32-bit words

__device__ __forceinline__ uint32_t pack2(__nv_bfloat16 a, __nv_bfloat16 b) {
    uint16_t ua = *reinterpret_cast<uint16_t*>(&a);
    uint16_t ub = *reinterpret_cast<uint16_t*>(&b);
    return (uint32_t)ua | ((uint32_t)ub << 16);
}

__device__ __forceinline__ void mma_bf16(float* d, const uint32_t* a,
                                         uint32_t b0, uint32_t b1) {
    asm volatile(
        "mma.sync.aligned.m16n8k16.row.col.f32.bf16.bf16.f32 "
        "{%0,%1,%2,%3},{%4,%5,%6,%7},{%8,%9},{%0,%1,%2,%3};\n"
        : "+f"(d[0]), "+f"(d[1]), "+f"(d[2]), "+f"(d[3])
        : "r"(a[0]), "r"(a[1]), "r"(a[2]), "r"(a[3]), "r"(b0), "r"(b1));
}

__global__ void __launch_bounds__(256)
gemm1_mma_kernel(const float* __restrict__ A, const float* __restrict__ bias) {
    __shared__ uint32_t asH[128 * GP], asL[128 * GP];
    __shared__ uint32_t bsH[128 * GP], bsL[128 * GP];
    const int tid = threadIdx.x;
    const int brow = blockIdx.x * 128;
    const int warp = tid >> 5, lane = tid & 31;
    const int wm = warp >> 1, wn = warp & 1;
    const int ldrow = tid >> 1, half = tid & 1;

    float acc[2][8][4];
#pragma unroll
    for (int mt = 0; mt < 2; mt++)
#pragma unroll
        for (int nt = 0; nt < 8; nt++)
#pragma unroll
            for (int q = 0; q < 4; q++) acc[mt][nt][q] = 0.f;

    const int arow = min(brow + ldrow, N_NODES - 1);
    const float4* __restrict__ ag =
        (const float4*)&A[(size_t)arow * IN_DIM + half * 16];
    const uint4* __restrict__ bgh =
        (const uint4*)&g_w_hi[ldrow * IN_DIM + half * 16];
    const uint4* __restrict__ bgl =
        (const uint4*)&g_w_lo[ldrow * IN_DIM + half * 16];

    for (int k0 = 0; k0 < IN_DIM; k0 += 32) {
#pragma unroll
        for (int q = 0; q < 4; q++) {
            float4 v = ag[(k0 >> 2) + q];
            __nv_bfloat16 hx = __float2bfloat16_rn(v.x);
            __nv_bfloat16 hy = __float2bfloat16_rn(v.y);
            __nv_bfloat16 hz = __float2bfloat16_rn(v.z);
            __nv_bfloat16 hw = __float2bfloat16_rn(v.w);
            __nv_bfloat16 lx = __float2bfloat16_rn(v.x - __bfloat162float(hx));
            __nv_bfloat16 ly = __float2bfloat16_rn(v.y - __bfloat162float(hy));
            __nv_bfloat16 lz = __float2bfloat16_rn(v.z - __bfloat162float(hz));
            __nv_bfloat16 lw = __float2bfloat16_rn(v.w - __bfloat162float(hw));
            int w = half * 8 + q * 2;
            *(uint2*)&asH[ldrow * GP + w] = make_uint2(pack2(hx, hy), pack2(hz, hw));
            *(uint2*)&asL[ldrow * GP + w] = make_uint2(pack2(lx, ly), pack2(lz, lw));
        }
#pragma unroll
        for (int q = 0; q < 2; q++) {
            uint4 bh = bgh[(k0 >> 3) + q];
            uint4 bl = bgl[(k0 >> 3) + q];
            *(uint4*)&bsH[ldrow * GP + half * 8 + q * 4] = bh;
            *(uint4*)&bsL[ldrow * GP + half * 8 + q * 4] = bl;
        }
        __syncthreads();
#pragma unroll
        for (int kk = 0; kk < 2; kk++) {
            const int kw = kk * 8 + (lane & 3);
            uint32_t aH[2][4], aL[2][4];
#pragma unroll
            for (int mt = 0; mt < 2; mt++) {
                int r = wm * 32 + mt * 16 + (lane >> 2);
                aH[mt][0] = asH[r * GP + kw];
                aH[mt][1] = asH[(r + 8) * GP + kw];
                aH[mt][2] = asH[r * GP + kw + 4];
                aH[mt][3] = asH[(r + 8) * GP + kw + 4];
                aL[mt][0] = asL[r * GP + kw];
                aL[mt][1] = asL[(r + 8) * GP + kw];
                aL[mt][2] = asL[r * GP + kw + 4];
                aL[mt][3] = asL[(r + 8) * GP + kw + 4];
            }
#pragma unroll
            for (int nt = 0; nt < 8; nt++) {
                int n = wn * 64 + nt * 8 + (lane >> 2);
                uint32_t bH0 = bsH[n * GP + kw], bH1 = bsH[n * GP + kw + 4];
                uint32_t bL0 = bsL[n * GP + kw], bL1 = bsL[n * GP + kw + 4];
#pragma unroll
                for (int mt = 0; mt < 2; mt++) {
                    mma_bf16(acc[mt][nt], aH[mt], bH0, bH1);
                    mma_bf16(acc[mt][nt], aL[mt], bH0, bH1);
                    mma_bf16(acc[mt][nt], aH[mt], bL0, bL1);
                }
            }
        }
        __syncthreads();
    }
    // epilogue: bias + relu -> fp16 store only
#pragma unroll
    for (int mt = 0; mt < 2; mt++) {
        int r0 = brow + wm * 32 + mt * 16 + (lane >> 2);
#pragma unroll
        for (int nt = 0; nt < 8; nt++) {
            int c = wn * 64 + nt * 8 + (lane & 3) * 2;
            float b0 = __ldg(&bias[c]), b1 = __ldg(&bias[c + 1]);
            if (r0 < N_NODES) {
                float v0 = fmaxf(acc[mt][nt][0] + b0, 0.f);
                float v1 = fmaxf(acc[mt][nt][1] + b1, 0.f);
                *(__half2*)&g_h0h[(size_t)r0 * HIDDEN + c] = __floats2half2_rn(v0, v1);
            }
            if (r0 + 8 < N_NODES) {
                float v0 = fmaxf(acc[mt][nt][2] + b0, 0.f);
                float v1 = fmaxf(acc[mt][nt][3] + b1, 0.f);
                *(__half2*)&g_h0h[(size_t)(r0 + 8) * HIDDEN + c] = __floats2half2_rn(v0, v1);
            }
        }
    }
}

// ---------------- CSR build (branch B) ---------------------------------------
__global__ void zero_counts_kernel() {
    int i = blockIdx.x * blockDim.x + threadIdx.x;
    if (i < N_NODES) g_counts[i] = 0;
}
__global__ void hist_kernel(const int* __restrict__ dst) {
    int i = blockIdx.x * blockDim.x + threadIdx.x;
    if (i < N_EDGES) atomicAdd(&g_counts[dst[i]], 1);
}
__global__ void scan_blocks_kernel() {
    __shared__ int wsum[32];
    const int t = threadIdx.x, lane = t & 31, wid = t >> 5;
    const int i = blockIdx.x * 1024 + t;
    int v = (i < N_NODES) ? g_counts[i] : 0;
    int x = v;
#pragma unroll
    for (int off = 1; off < 32; off <<= 1) {
        int y = __shfl_up_sync(0xffffffffu, x, off);
        if (lane >= off) x += y;
    }
    if (lane == 31) wsum[wid] = x;
    __syncthreads();
    if (wid == 0) {
        int s = wsum[lane];
#pragma unroll
        for (int off = 1; off < 32; off <<= 1) {
            int y = __shfl_up_sync(0xffffffffu, s, off);
            if (lane >= off) s += y;
        }
        wsum[lane] = s;
    }
    __syncthreads();
    int incl = x + (wid > 0 ? wsum[wid - 1] : 0);
    if (i < N_NODES) g_rowptr[i] = incl - v;
    if (t == 1023) g_blocksums[blockIdx.x] = incl;
}
__global__ void scan_sums_kernel() {
    __shared__ int sm[64];
    int t = threadIdx.x;
    int v = (t < SCAN_NB) ? g_blocksums[t] : 0;
    sm[t] = v;
    __syncthreads();
    for (int off = 1; off < 64; off <<= 1) {
        int x = (t >= off) ? sm[t - off] : 0;
        __syncthreads();
        sm[t] += x;
        __syncthreads();
    }
    if (t < SCAN_NB) g_blocksums[t] = sm[t] - v;
}
__global__ void add_offsets_kernel() {
    int i = blockIdx.x * blockDim.x + threadIdx.x;
    if (i < N_NODES) {
        int r = g_rowptr[i] + g_blocksums[i >> 10];
        g_rowptr[i] = r;
        g_cursor[i] = r;
    }
    if (i == 0) g_rowptr[N_NODES] = N_EDGES;
}
__global__ void scatter_kernel(const int* __restrict__ src,
                               const int* __restrict__ dst) {
    int i = blockIdx.x * blockDim.x + threadIdx.x;
    if (i < N_EDGES) {
        int t = dst[i];
        int pos = atomicAdd(&g_cursor[t], 1);
        g_psrc[pos] = src[i];
        g_pdst[pos] = t;
    }
}

// ---------------- gate scalar projections (layer 0, fp16 input) --------------
__global__ void gate_proj_kernel(const float* __restrict__ gate_w) {
    int warp = (blockIdx.x * blockDim.x + threadIdx.x) >> 5;
    int lane = threadIdx.x & 31;
    if (warp >= N_NODES) return;
    const float4 wd = *(const float4*)&gate_w[lane * 4];
    const float4 ws = *(const float4*)&gate_w[HIDDEN + lane * 4];
    uint2 q = *(const uint2*)&g_h0h[(size_t)warp * HIDDEN + lane * 4];
    __half2 qa = *reinterpret_cast<__half2*>(&q.x);
    __half2 qb = *reinterpret_cast<__half2*>(&q.y);
    float2 fa = __half22float2(qa), fb = __half22float2(qb);
    float a0 = fa.x * wd.x + fa.y * wd.y + fb.x * wd.z + fb.y * wd.w;
    float a1 = fa.x * ws.x + fa.y * ws.y + fb.x * ws.z + fb.y * ws.w;
#pragma unroll
    for (int off = 16; off; off >>= 1) {
        a0 += __shfl_xor_sync(0xffffffffu, a0, off);
        a1 += __shfl_xor_sync(0xffffffffu, a1, off);
    }
    if (lane == 0) { g_sdst[warp] = a0; g_ssrc[warp] = a1; }
}

// ---------------- per-position edge coefficients (coalesced) ----------------
__global__ void edge_coef_kernel(const float* __restrict__ d,
                                 const float* __restrict__ gate_b, int layer) {
    int p = blockIdx.x * blockDim.x + threadIdx.x;
    if (p >= N_EDGES) return;
    int s = g_psrc[p], t = g_pdst[p];
    float g = tanhf(g_sdst[t] + g_ssrc[s] + gate_b[layer]);
    g_pedge[p] = make_int2(s, __float_as_int(g * d[t] * d[s]));
}

// ---------------- aggregation (fp16 gathers, fp32 accumulate, MLP=8) --------
__device__ __forceinline__ float4 h4_to_f4(uint2 q) {
    __half2 a = *reinterpret_cast<__half2*>(&q.x);
    __half2 b = *reinterpret_cast<__half2*>(&q.y);
    float2 fa = __half22float2(a), fb = __half22float2(b);
    return make_float4(fa.x, fa.y, fb.x, fb.y);
}

// LAYER 0: gather g_h0h -> g_hAh fp16, + fused layer-1 gate scalars.
// LAYER 1: gather g_hAh -> g_hB fp32.
template <int LAYER>
__global__ void agg_kernel(const float* __restrict__ gate_w_next) {
    int warp = (blockIdx.x * blockDim.x + threadIdx.x) >> 5;
    int lane = threadIdx.x & 31;
    if (warp >= N_NODES) return;
    const __half* __restrict__ h_in = (LAYER == 0) ? g_h0h : g_hAh;
    int rs = g_rowptr[warp], re = g_rowptr[warp + 1];
    float4 acc = make_float4(0.f, 0.f, 0.f, 0.f);
    int p = rs;
    // MLP=8 main loop: 8 independent gathers in flight
    for (; p + 7 < re; p += 8) {
        int2 e[8];
        uint2 q[8];
#pragma unroll
        for (int i = 0; i < 8; i++) e[i] = __ldg(&g_pedge[p + i]);
#pragma unroll
        for (int i = 0; i < 8; i++)
            q[i] = *(const uint2*)&h_in[(size_t)e[i].x * HIDDEN + lane * 4];
#pragma unroll
        for (int i = 0; i < 8; i++) {
            float c = __int_as_float(e[i].y);
            float4 hv = h4_to_f4(q[i]);
            acc.x = fmaf(c, hv.x, acc.x);
            acc.y = fmaf(c, hv.y, acc.y);
            acc.z = fmaf(c, hv.z, acc.z);
            acc.w = fmaf(c, hv.w, acc.w);
        }
    }
    // MLP=4 step
    for (; p + 3 < re; p += 4) {
        int2 e[4];
        uint2 q[4];
#pragma unroll
        for (int i = 0; i < 4; i++) e[i] = __ldg(&g_pedge[p + i]);
#pragma unroll
        for (int i = 0; i < 4; i++)
            q[i] = *(const uint2*)&h_in[(size_t)e[i].x * HIDDEN + lane * 4];
#pragma unroll
        for (int i = 0; i < 4; i++) {
            float c = __int_as_float(e[i].y);
            float4 hv = h4_to_f4(q[i]);
            acc.x = fmaf(c, hv.x, acc.x);
            acc.y = fmaf(c, hv.y, acc.y);
            acc.z = fmaf(c, hv.z, acc.z);
            acc.w = fmaf(c, hv.w, acc.w);
        }
    }
    for (; p < re; ++p) {
        int2 e = __ldg(&g_pedge[p]);
        float ev = __int_as_float(e.y);
        float4 hv = h4_to_f4(*(const uint2*)&h_in[(size_t)e.x * HIDDEN + lane * 4]);
        acc.x = fmaf(ev, hv.x, acc.x);
        acc.y = fmaf(ev, hv.y, acc.y);
        acc.z = fmaf(ev, hv.z, acc.z);
        acc.w = fmaf(ev, hv.w, acc.w);
    }
    // residual from fp16 raw
    float4 rv = h4_to_f4(*(const uint2*)&g_h0h[(size_t)warp * HIDDEN + lane * 4]);
    float4 o;
    o.x = fmaf(EPS_F, rv.x, acc.x);
    o.y = fmaf(EPS_F, rv.y, acc.y);
    o.z = fmaf(EPS_F, rv.z, acc.z);
    o.w = fmaf(EPS_F, rv.w, acc.w);

    if (LAYER == 0) {
        uint2 st;
        __half2 p01 = __floats2half2_rn(o.x, o.y);
        __half2 p23 = __floats2half2_rn(o.z, o.w);
        st.x = *reinterpret_cast<uint32_t*>(&p01);
        st.y = *reinterpret_cast<uint32_t*>(&p23);
        *(uint2*)&g_hAh[(size_t)warp * HIDDEN + lane * 4] = st;
        // fused next-layer gate scalars (fp32 from registers)
        float4 wd = *(const float4*)&gate_w_next[lane * 4];
        float4 ws = *(const float4*)&gate_w_next[HIDDEN + lane * 4];
        float a0 = o.x * wd.x + o.y * wd.y + o.z * wd.z + o.w * wd.w;
        float a1 = o.x * ws.x + o.y * ws.y + o.z * ws.z + o.w * ws.w;
#pragma unroll
        for (int off = 16; off; off >>= 1) {
            a0 += __shfl_xor_sync(0xffffffffu, a0, off);
            a1 += __shfl_xor_sync(0xffffffffu, a1, off);
        }
        if (lane == 0) { g_sdst[warp] = a0; g_ssrc[warp] = a1; }
    } else {
        *(float4*)&g_hB[(size_t)warp * HIDDEN + lane * 4] = o;
    }
}

// ---------------- final: out = log_softmax(h @ t2_w^T + t2_b) ---------------
// 64 threads/block (2 warps), 8 nodes per warp: halves wt LDS traffic.
__global__ void __launch_bounds__(64)
out_kernel(const float* __restrict__ W2, const float* __restrict__ b2,
           float* __restrict__ out) {
    __shared__ float wt[HIDDEN * OUT_DIM];   // 32KB
    __shared__ float b2s[OUT_DIM];
    __shared__ float hrow[2][8][HIDDEN];     // 8KB
    for (int idx = threadIdx.x; idx < OUT_DIM * HIDDEN; idx += blockDim.x) {
        int j = idx >> 7;
        int k = idx & 127;
        wt[k * OUT_DIM + j] = W2[idx];
    }
    if (threadIdx.x < OUT_DIM) b2s[threadIdx.x] = b2[threadIdx.x];
    __syncthreads();

    const int lane = threadIdx.x & 31;
    const int wlocal = threadIdx.x >> 5;
    const int nwarps = (gridDim.x * blockDim.x) >> 5;

    for (int n0 = (((blockIdx.x * blockDim.x + threadIdx.x) >> 5) << 3);
         n0 < N_NODES; n0 += nwarps * 8) {
#pragma unroll
        for (int i = 0; i < 8; i++) {
            int n = min(n0 + i, N_NODES - 1);
            *(float4*)&hrow[wlocal][i][lane * 4] =
                *(const float4*)&g_hB[(size_t)n * HIDDEN + lane * 4];
        }
        __syncwarp();

        float acc0[8], acc1[8];
#pragma unroll
        for (int i = 0; i < 8; i++) { acc0[i] = b2s[lane]; acc1[i] = b2s[lane + 32]; }
#pragma unroll 4
        for (int k = 0; k < HIDDEN; k++) {
            float w0 = wt[k * OUT_DIM + lane];
            float w1 = wt[k * OUT_DIM + lane + 32];
#pragma unroll
            for (int i = 0; i < 8; i++) {
                float hk = hrow[wlocal][i][k];
                acc0[i] = fmaf(hk, w0, acc0[i]);
                acc1[i] = fmaf(hk, w1, acc1[i]);
            }
        }
#pragma unroll
        for (int i = 0; i < 8; i++) {
            int n = n0 + i;
            if (n >= N_NODES) break;
            float m = fmaxf(acc0[i], acc1[i]);
#pragma unroll
            for (int off = 16; off; off >>= 1)
                m = fmaxf(m, __shfl_xor_sync(0xffffffffu, m, off));
            float s = expf(acc0[i] - m) + expf(acc1[i] - m);
#pragma unroll
            for (int off = 16; off; off >>= 1)
                s += __shfl_xor_sync(0xffffffffu, s, off);
            float lse = m + logf(s);
            out[(size_t)n * OUT_DIM + lane]      = acc0[i] - lse;
            out[(size_t)n * OUT_DIM + lane + 32] = acc1[i] - lse;
        }
        __syncwarp();
    }
}

// ---------------- launch ----------------------------------------------------
extern "C" void kernel_launch(void* const* d_in, const int* in_sizes, int n_in,
                              void* d_out, int out_size) {
    const float* h      = (const float*)d_in[0];
    const int*   src    = (const int*)d_in[1];
    const int*   dst    = (const int*)d_in[2];
    const float* d      = (const float*)d_in[3];
    const float* t1_w   = (const float*)d_in[4];
    const float* t1_b   = (const float*)d_in[5];
    const float* gate_w = (const float*)d_in[6];
    const float* gate_b = (const float*)d_in[7];
    const float* t2_w   = (const float*)d_in[8];
    const float* t2_b   = (const float*)d_in[9];
    float* out = (float*)d_out;

    // Fork: branch B (CSR build) runs concurrently with branch A (GEMM chain).
    cudaStream_t s2;
    cudaStreamCreate(&s2);
    cudaEvent_t evFork, evJoin;
    cudaEventCreateWithFlags(&evFork, cudaEventDisableTiming);
    cudaEventCreateWithFlags(&evJoin, cudaEventDisableTiming);

    cudaEventRecord(evFork, 0);
    cudaStreamWaitEvent(s2, evFork, 0);

    // --- branch B on s2: CSR build (only reads src/dst) ---
    zero_counts_kernel<<<(N_NODES + 255) / 256, 256, 0, s2>>>();
    hist_kernel<<<(N_EDGES + 255) / 256, 256, 0, s2>>>(dst);
    scan_blocks_kernel<<<SCAN_NB, 1024, 0, s2>>>();
    scan_sums_kernel<<<1, 64, 0, s2>>>();
    add_offsets_kernel<<<(N_NODES + 255) / 256, 256, 0, s2>>>();
    scatter_kernel<<<(N_EDGES + 255) / 256, 256, 0, s2>>>(src, dst);
    cudaEventRecord(evJoin, s2);

    // --- branch A on main stream: transform + gate scalars ---
    wconv_kernel<<<(HIDDEN * IN_DIM + 255) / 256, 256>>>(t1_w);
    gemm1_mma_kernel<<<(N_NODES + 127) / 128, 256>>>(h, t1_b);

    const int node_warp_blocks = (N_NODES * 32 + 255) / 256;  // 6250
    const int edge_blocks = (N_EDGES + 255) / 256;

    gate_proj_kernel<<<node_warp_blocks, 256>>>(gate_w);

    // join: edge_coef needs both branches
    cudaStreamWaitEvent(0, evJoin, 0);

    // layer 0: g_h0h -> g_hAh (+ fused layer-1 gate scalars)
    edge_coef_kernel<<<edge_blocks, 256>>>(d, gate_b, 0);
    agg_kernel<0><<<node_warp_blocks, 256>>>(gate_w + 2 * HIDDEN);

    // layer 1: g_hAh -> g_hB
    edge_coef_kernel<<<edge_blocks, 256>>>(d, gate_b, 1);
    agg_kernel<1><<<node_warp_blocks, 256>>>(nullptr);

    // output head + log_softmax (8 nodes/warp)
    out_kernel<<<592, 64>>>(t2_w, t2_b, out);

    cudaStreamDestroy(s2);
    cudaEventDestroy(evFork);
    cudaEventDestroy(evJoin);
}